// round 5
// baseline (speedup 1.0000x reference)
#include <cuda_runtime.h>
#include <cuda_fp16.h>
#include <math.h>

// ---------------------------------------------------------------------------
// GATEdgeNet: 2x GATConv (single head) + edge MLP.
// GEMMs accumulate fp32; gathered tensors (h1, h2, U, V) stored fp16 to halve
// L2 gather traffic. GAT softmax computed in ONE pass (no segment-max: the
// ratio w/sum(w) is invariant to the max shift and logits are bounded).
// ---------------------------------------------------------------------------

constexpr int NN = 50000;
constexpr int NE = 800000;
constexpr int ET = 2 * NE + NN;   // 1,650,000

// ---- scratch (static device arrays; no runtime alloc allowed) --------------
__device__ unsigned short g_h1[NN * 128];   // fp16  (only 64 cols used? no: 128? h1 is NNx128)
__device__ unsigned short g_h2[NN * 64];    // fp16
__device__ unsigned short g_U[NN * 128];    // fp16
__device__ unsigned short g_V[NN * 128];    // fp16
__device__ float g_f1[NN * 128];
__device__ float g_xf[NN * 128];
__device__ float g_s1[NN];
__device__ float g_t1[NN];
__device__ float g_s2[NN];
__device__ float g_t2[NN];
__device__ int   g_deg[NN];
__device__ int   g_rowptr[NN + 1];
__device__ int   g_cursor[NN];
__device__ int   g_adj[ET];

// ---------------------------------------------------------------------------
__device__ __forceinline__ void edge_sd(int t, const int* __restrict__ ei,
                                        int& src, int& dst) {
    if (t < NE) {            // forward copy:  src=row, dst=col
        src = ei[2 * t];
        dst = ei[2 * t + 1];
    } else if (t < 2 * NE) { // reversed copy: src=col, dst=row
        int u = t - NE;
        src = ei[2 * u + 1];
        dst = ei[2 * u];
    } else {                 // self loop
        src = dst = t - 2 * NE;
    }
}

__global__ void k_hist(const int* __restrict__ ei) {
    for (int t = blockIdx.x * blockDim.x + threadIdx.x; t < ET;
         t += gridDim.x * blockDim.x) {
        int s, d;
        edge_sd(t, ei, s, d);
        atomicAdd(&g_deg[d], 1);
    }
}

// ---------------------------------------------------------------------------
// Single-block scan: register-chunked, warp-shuffle, 2 barriers total.
// ---------------------------------------------------------------------------
__global__ void __launch_bounds__(1024) k_scan() {
    constexpr int CH = (NN + 1023) / 1024;    // 49 per thread
    __shared__ int wsum[32];
    const int tid  = threadIdx.x;
    const int lane = tid & 31;
    const int wid  = tid >> 5;
    const int base = tid * CH;

    int vals[CH];
    int s = 0;
    #pragma unroll
    for (int k = 0; k < CH; k++) {
        int i = base + k;
        int v = (i < NN) ? g_deg[i] : 0;
        vals[k] = v;
        s += v;
    }
    int x = s;
    #pragma unroll
    for (int off = 1; off < 32; off <<= 1) {
        int y = __shfl_up_sync(0xffffffffu, x, off);
        if (lane >= off) x += y;
    }
    if (lane == 31) wsum[wid] = x;
    __syncthreads();
    if (wid == 0) {
        int w = wsum[lane];
        #pragma unroll
        for (int off = 1; off < 32; off <<= 1) {
            int y = __shfl_up_sync(0xffffffffu, w, off);
            if (lane >= off) w += y;
        }
        wsum[lane] = w;
    }
    __syncthreads();

    int run = x - s + (wid ? wsum[wid - 1] : 0);
    if (tid == 0) g_rowptr[0] = 0;
    #pragma unroll
    for (int k = 0; k < CH; k++) {
        int i = base + k;
        if (i < NN) {
            g_cursor[i] = run;
            run += vals[k];
            g_rowptr[i + 1] = run;
        }
    }
}

__global__ void k_fill(const int* __restrict__ ei) {
    for (int t = blockIdx.x * blockDim.x + threadIdx.x; t < ET;
         t += gridDim.x * blockDim.x) {
        int s, d;
        edge_sd(t, ei, s, d);
        int pos = atomicAdd(&g_cursor[d], 1);
        g_adj[pos] = s;
    }
}

__global__ void k_copyx(const float* __restrict__ x) {
    const int total = NN * 16;
    for (int i = blockIdx.x * blockDim.x + threadIdx.x; i < total;
         i += gridDim.x * blockDim.x) {
        int n = i >> 4, q = i & 15;
        *reinterpret_cast<float4*>(g_xf + (size_t)n * 128 + q * 4) =
            reinterpret_cast<const float4*>(x)[i];
    }
}

// ---------------------------------------------------------------------------
// SGEMM: C[M x BN] = A[M x K] * B[K x BN] (fp32 in, fp32 accum, fp16 out).
// 128 x BN tile, 256 threads, 8 x (BN/16) register tile, BK=8,
// double-buffered shared with register prefetch.
// ---------------------------------------------------------------------------
template <int BN, int K>
__global__ void __launch_bounds__(256)
k_sgemm_h(const float* __restrict__ A, const float* __restrict__ B,
          __half* __restrict__ C, int M) {
    constexpr int BM = 128, BK = 8, TN = BN / 16;
    constexpr int NSTEP = K / BK;
    __shared__ float As[2][BK][BM];
    __shared__ float Bs[2][BK][BN];

    const int tid = threadIdx.x;
    const int bm  = blockIdx.x * BM;
    const int tx  = tid & 15;
    const int ty  = tid >> 4;

    float acc[8][TN];
    #pragma unroll
    for (int i = 0; i < 8; i++)
        #pragma unroll
        for (int j = 0; j < TN; j++) acc[i][j] = 0.f;

    const int a_m = tid >> 1;
    const int a_k = (tid & 1) * 4;
    int a_row = bm + a_m;
    if (a_row >= M) a_row = M - 1;   // clamp: bogus rows never stored
    const float* Aptr = A + (size_t)a_row * K + a_k;

    const int b_k = (BN == 128) ? (tid >> 5) : (tid >> 4);
    const int b_n = (BN == 128) ? ((tid & 31) << 2) : ((tid & 15) << 2);
    const bool b_act = (BN == 128) || (tid < 128);

    float4 av = *reinterpret_cast<const float4*>(Aptr);
    float4 bv = b_act ? *reinterpret_cast<const float4*>(B + (size_t)b_k * BN + b_n)
                      : make_float4(0.f, 0.f, 0.f, 0.f);
    As[0][a_k + 0][a_m] = av.x;
    As[0][a_k + 1][a_m] = av.y;
    As[0][a_k + 2][a_m] = av.z;
    As[0][a_k + 3][a_m] = av.w;
    if (b_act) *reinterpret_cast<float4*>(&Bs[0][b_k][b_n]) = bv;
    __syncthreads();

    int buf = 0;
    #pragma unroll
    for (int step = 0; step < NSTEP; step++) {
        const int k0 = step * BK;
        if (step + 1 < NSTEP) {
            av = *reinterpret_cast<const float4*>(Aptr + k0 + BK);
            if (b_act)
                bv = *reinterpret_cast<const float4*>(
                    B + (size_t)(k0 + BK + b_k) * BN + b_n);
        }
        #pragma unroll
        for (int k = 0; k < BK; k++) {
            float ra[8];
            {
                float4 r0 = *reinterpret_cast<const float4*>(&As[buf][k][ty * 8]);
                float4 r1 = *reinterpret_cast<const float4*>(&As[buf][k][ty * 8 + 4]);
                ra[0] = r0.x; ra[1] = r0.y; ra[2] = r0.z; ra[3] = r0.w;
                ra[4] = r1.x; ra[5] = r1.y; ra[6] = r1.z; ra[7] = r1.w;
            }
            float rb[TN];
            #pragma unroll
            for (int jj = 0; jj < TN; jj += 4) {
                float4 q = *reinterpret_cast<const float4*>(&Bs[buf][k][tx * TN + jj]);
                rb[jj] = q.x; rb[jj + 1] = q.y; rb[jj + 2] = q.z; rb[jj + 3] = q.w;
            }
            #pragma unroll
            for (int i = 0; i < 8; i++)
                #pragma unroll
                for (int j = 0; j < TN; j++)
                    acc[i][j] = fmaf(ra[i], rb[j], acc[i][j]);
        }
        if (step + 1 < NSTEP) {
            const int nb = buf ^ 1;
            As[nb][a_k + 0][a_m] = av.x;
            As[nb][a_k + 1][a_m] = av.y;
            As[nb][a_k + 2][a_m] = av.z;
            As[nb][a_k + 3][a_m] = av.w;
            if (b_act) *reinterpret_cast<float4*>(&Bs[nb][b_k][b_n]) = bv;
            __syncthreads();
            buf = nb;
        }
    }

    #pragma unroll
    for (int i = 0; i < 8; i++) {
        int row = bm + ty * 8 + i;
        if (row < M) {
            __half2* cp = reinterpret_cast<__half2*>(
                C + (size_t)row * BN + tx * TN);
            #pragma unroll
            for (int j = 0; j < TN; j += 2)
                cp[j >> 1] = __floats2half2_rn(acc[i][j], acc[i][j + 1]);
        }
    }
}

// ---------------------------------------------------------------------------
// per-row dots on fp16 h: s[i] = h[i].a_src, t[i] = h[i].a_dst (warp per row)
// ---------------------------------------------------------------------------
template <int C>
__global__ void k_rowdots(const __half* __restrict__ h,
                          const float* __restrict__ asrc,
                          const float* __restrict__ adst,
                          float* __restrict__ s, float* __restrict__ t) {
    int w = (blockIdx.x * blockDim.x + threadIdx.x) >> 5;
    int lane = threadIdx.x & 31;
    if (w >= NN) return;
    const __half2* hr = reinterpret_cast<const __half2*>(h + (size_t)w * C);
    float ds = 0.f, dt = 0.f;
    #pragma unroll
    for (int p = lane; p < C / 2; p += 32) {
        float2 v = __half22float2(hr[p]);
        ds = fmaf(v.x, __ldg(asrc + 2 * p), fmaf(v.y, __ldg(asrc + 2 * p + 1), ds));
        dt = fmaf(v.x, __ldg(adst + 2 * p), fmaf(v.y, __ldg(adst + 2 * p + 1), dt));
    }
    #pragma unroll
    for (int o = 16; o; o >>= 1) {
        ds += __shfl_xor_sync(0xffffffffu, ds, o);
        dt += __shfl_xor_sync(0xffffffffu, dt, o);
    }
    if (lane == 0) { s[w] = ds; t[w] = dt; }
}

// ---------------------------------------------------------------------------
// GAT aggregation, warp per dst node, SINGLE PASS (no segment max: alpha is
// shift-invariant and logits are bounded, so exp never overflows fp32).
// ---------------------------------------------------------------------------
template <int C>
__global__ void k_gatagg(const __half* __restrict__ h,
                         const float* __restrict__ s,
                         const float* __restrict__ t,
                         const float* __restrict__ bias,
                         float* __restrict__ out, int ostride, int ocoloff) {
    constexpr int CPL = C / 32;
    int w = (blockIdx.x * blockDim.x + threadIdx.x) >> 5;
    int lane = threadIdx.x & 31;
    if (w >= NN) return;

    const int beg = g_rowptr[w];
    const int end = g_rowptr[w + 1];
    const float tn = t[w];

    float denom = 0.f;
    float acc[CPL];
    #pragma unroll
    for (int q = 0; q < CPL; q++) acc[q] = 0.f;

    for (int j0 = beg; j0 < end; j0 += 32) {
        int j = j0 + lane;
        float wv = 0.f;
        int sj = 0;
        if (j < end) {
            sj = g_adj[j];
            float e = s[sj] + tn;
            e = (e >= 0.f) ? e : 0.2f * e;
            wv = __expf(e);
        }
        denom += wv;
        int cnt = end - j0;
        if (cnt > 32) cnt = 32;
        for (int k = 0; k < cnt; k++) {
            float wk = __shfl_sync(0xffffffffu, wv, k);
            int   sk = __shfl_sync(0xffffffffu, sj, k);
            if (CPL == 4) {
                uint2 raw = *reinterpret_cast<const uint2*>(
                    h + (size_t)sk * C + lane * 4);
                float2 lo = __half22float2(*reinterpret_cast<__half2*>(&raw.x));
                float2 hi = __half22float2(*reinterpret_cast<__half2*>(&raw.y));
                acc[0] = fmaf(wk, lo.x, acc[0]);
                acc[1] = fmaf(wk, lo.y, acc[1]);
                acc[2] = fmaf(wk, hi.x, acc[2]);
                acc[3] = fmaf(wk, hi.y, acc[3]);
            } else {
                __half2 raw = *reinterpret_cast<const __half2*>(
                    h + (size_t)sk * C + lane * 2);
                float2 v = __half22float2(raw);
                acc[0] = fmaf(wk, v.x, acc[0]);
                acc[1] = fmaf(wk, v.y, acc[1]);
            }
        }
    }
    #pragma unroll
    for (int o = 16; o; o >>= 1)
        denom += __shfl_xor_sync(0xffffffffu, denom, o);

    const float inv = 1.f / (denom + 1e-16f);
    float* op = out + (size_t)w * ostride + ocoloff + lane * CPL;
    if (CPL == 4) {
        float4 r;
        r.x = fmaxf(acc[0] * inv + __ldg(bias + lane * 4 + 0), 0.f);
        r.y = fmaxf(acc[1] * inv + __ldg(bias + lane * 4 + 1), 0.f);
        r.z = fmaxf(acc[2] * inv + __ldg(bias + lane * 4 + 2), 0.f);
        r.w = fmaxf(acc[3] * inv + __ldg(bias + lane * 4 + 3), 0.f);
        *reinterpret_cast<float4*>(op) = r;
    } else {
        float2 r;
        r.x = fmaxf(acc[0] * inv + __ldg(bias + lane * 2 + 0), 0.f);
        r.y = fmaxf(acc[1] * inv + __ldg(bias + lane * 2 + 1), 0.f);
        *reinterpret_cast<float2*>(op) = r;
    }
}

// ---------------------------------------------------------------------------
// Edge MLP: warp per edge, U/V gathered in fp16.
//   out[e] = sigmoid( relu(U[row]+V[col]+d@W_d+b1) . W_m2 + b2 )
// ---------------------------------------------------------------------------
__global__ void __launch_bounds__(256)
k_edgemlp(const int* __restrict__ ei, const float* __restrict__ ed,
          const __half* __restrict__ U, const __half* __restrict__ V,
          const float* __restrict__ Wm1, const float* __restrict__ b1,
          const float* __restrict__ Wm2, const float* __restrict__ b2,
          float* __restrict__ out) {
    __shared__ float sWd[16 * 128];
    __shared__ float sB1[128];
    __shared__ float sW2[128];
    const int tid = threadIdx.x;
    for (int i = tid; i < 16 * 128; i += 256)
        sWd[i] = Wm1[256 * 128 + i];       // rows 256..271 of W_m1
    if (tid < 128) {
        sB1[tid] = b1[tid];
        sW2[tid] = Wm2[tid];
    }
    __syncthreads();

    const int e = blockIdx.x * 8 + (tid >> 5);
    const int lane = tid & 31;
    if (e >= NE) return;

    const int row = ei[2 * e];
    const int col = ei[2 * e + 1];

    uint2 ur = *reinterpret_cast<const uint2*>(U + (size_t)row * 128 + lane * 4);
    uint2 vr = *reinterpret_cast<const uint2*>(V + (size_t)col * 128 + lane * 4);
    float2 u01 = __half22float2(*reinterpret_cast<__half2*>(&ur.x));
    float2 u23 = __half22float2(*reinterpret_cast<__half2*>(&ur.y));
    float2 v01 = __half22float2(*reinterpret_cast<__half2*>(&vr.x));
    float2 v23 = __half22float2(*reinterpret_cast<__half2*>(&vr.y));
    float4 bb = *reinterpret_cast<const float4*>(sB1 + lane * 4);
    float a0 = u01.x + v01.x + bb.x;
    float a1 = u01.y + v01.y + bb.y;
    float a2 = u23.x + v23.x + bb.z;
    float a3 = u23.y + v23.y + bb.w;

    const float4* dp = reinterpret_cast<const float4*>(ed + (size_t)e * 16);
    float4 d0 = dp[0], d1 = dp[1], d2 = dp[2], d3 = dp[3];
    float dv[16] = {d0.x, d0.y, d0.z, d0.w, d1.x, d1.y, d1.z, d1.w,
                    d2.x, d2.y, d2.z, d2.w, d3.x, d3.y, d3.z, d3.w};
    #pragma unroll
    for (int k = 0; k < 16; k++) {
        float4 wv = *reinterpret_cast<const float4*>(sWd + k * 128 + lane * 4);
        a0 = fmaf(dv[k], wv.x, a0);
        a1 = fmaf(dv[k], wv.y, a1);
        a2 = fmaf(dv[k], wv.z, a2);
        a3 = fmaf(dv[k], wv.w, a3);
    }
    a0 = fmaxf(a0, 0.f); a1 = fmaxf(a1, 0.f);
    a2 = fmaxf(a2, 0.f); a3 = fmaxf(a3, 0.f);

    float4 w2 = *reinterpret_cast<const float4*>(sW2 + lane * 4);
    float p = a0 * w2.x + a1 * w2.y + a2 * w2.z + a3 * w2.w;
    #pragma unroll
    for (int o = 16; o; o >>= 1)
        p += __shfl_xor_sync(0xffffffffu, p, o);

    if (lane == 0) {
        float z = p + __ldg(b2);
        out[e] = 1.f / (1.f + __expf(-z));
    }
}

// ---------------------------------------------------------------------------
extern "C" void kernel_launch(void* const* d_in, const int* in_sizes, int n_in,
                              void* d_out, int out_size) {
    const float* x    = (const float*)d_in[0];
    const int*   ei   = (const int*)  d_in[1];
    const float* ed   = (const float*)d_in[2];
    const float* Wg1  = (const float*)d_in[3];
    const float* a1s  = (const float*)d_in[4];
    const float* a1d  = (const float*)d_in[5];
    const float* bg1  = (const float*)d_in[6];
    const float* Wg2  = (const float*)d_in[7];
    const float* a2s  = (const float*)d_in[8];
    const float* a2d  = (const float*)d_in[9];
    const float* bg2  = (const float*)d_in[10];
    const float* Wm1  = (const float*)d_in[11];
    const float* bm1  = (const float*)d_in[12];
    const float* Wm2  = (const float*)d_in[13];
    const float* bm2  = (const float*)d_in[14];
    float* out = (float*)d_out;

    __half *h1, *h2, *U, *V;
    float *f1, *xf, *s1, *t1, *s2, *t2;
    int* degp;
    cudaGetSymbolAddress((void**)&h1, g_h1);
    cudaGetSymbolAddress((void**)&h2, g_h2);
    cudaGetSymbolAddress((void**)&U,  g_U);
    cudaGetSymbolAddress((void**)&V,  g_V);
    cudaGetSymbolAddress((void**)&f1, g_f1);
    cudaGetSymbolAddress((void**)&xf, g_xf);
    cudaGetSymbolAddress((void**)&s1, g_s1);
    cudaGetSymbolAddress((void**)&t1, g_t1);
    cudaGetSymbolAddress((void**)&s2, g_s2);
    cudaGetSymbolAddress((void**)&t2, g_t2);
    cudaGetSymbolAddress((void**)&degp, g_deg);

    const int warpBlocks = (NN * 32 + 255) / 256;   // 6250
    const int gemmBlocks = (NN + 127) / 128;        // 391

    // CSR build (dst-sorted adjacency, shared by both GAT layers)
    cudaMemsetAsync(degp, 0, NN * sizeof(int));
    k_copyx<<<1024, 256>>>(x);
    k_hist<<<2048, 256>>>(ei);
    k_scan<<<1, 1024>>>();
    k_fill<<<2048, 256>>>(ei);

    // GAT layer 1
    k_sgemm_h<128, 64><<<gemmBlocks, 256>>>(x, Wg1, h1, NN);
    k_rowdots<128><<<warpBlocks, 256>>>(h1, a1s, a1d, s1, t1);
    k_gatagg<128><<<warpBlocks, 256>>>(h1, s1, t1, bg1, f1, 128, 0);

    // GAT layer 2 (writes into right half of xf)
    k_sgemm_h<64, 128><<<gemmBlocks, 256>>>(f1, Wg2, h2, NN);
    k_rowdots<64><<<warpBlocks, 256>>>(h2, a2s, a2d, s2, t2);
    k_gatagg<64><<<warpBlocks, 256>>>(h2, s2, t2, bg2, xf, 128, 64);

    // Edge MLP, factored: U = xf @ Wm1[0:128], V = xf @ Wm1[128:256]
    k_sgemm_h<128, 128><<<gemmBlocks, 256>>>(xf, Wm1, U, NN);
    k_sgemm_h<128, 128><<<gemmBlocks, 256>>>(xf, Wm1 + 128 * 128, V, NN);
    k_edgemlp<<<NE / 8, 256>>>(ei, ed, U, V, Wm1, bm1, Wm2, bm2, out);
}

// round 6
// speedup vs baseline: 1.1459x; 1.1459x over previous
#include <cuda_runtime.h>
#include <cuda_fp16.h>
#include <math.h>

// ---------------------------------------------------------------------------
// GATEdgeNet: 2x GATConv (single head) + edge MLP.
//  - gathered tensors (h1,h2,U,V) in fp16 (halved L2 traffic)
//  - single-pass GAT softmax (shift-invariant, bounded logits)
//  - edge MLP with W_d in registers (no per-edge smem traffic)
//  - independent kernels fused by grid concatenation (9 graph nodes total)
// ---------------------------------------------------------------------------

constexpr int NN = 50000;
constexpr int NE = 800000;
constexpr int ET = 2 * NE + NN;   // 1,650,000

constexpr int GB128 = (NN + 127) / 128;   // 391 gemm blocks
constexpr int WB    = (NN * 32 + 255) / 256; // 6250 warp-per-node blocks
constexpr int HISTB = 2048;
constexpr int COPYB = 1024;
constexpr int MLPB  = 2048;               // edgemlp blocks (16384 warps)

// ---- scratch (static device arrays; no runtime alloc allowed) --------------
__device__ unsigned short g_h1[NN * 128];   // fp16
__device__ unsigned short g_h2[NN * 64];    // fp16
__device__ unsigned short g_U[NN * 128];    // fp16
__device__ unsigned short g_V[NN * 128];    // fp16
__device__ float g_f1[NN * 128];
__device__ float g_xf[NN * 128];
__device__ float g_s1[NN];
__device__ float g_t1[NN];
__device__ float g_s2[NN];
__device__ float g_t2[NN];
__device__ float g_w2s[128];
__device__ float g_w2d[128];
__device__ int   g_deg[NN];
__device__ int   g_rowptr[NN + 1];
__device__ int   g_cursor[NN];
__device__ int   g_adj[ET];

// ---------------------------------------------------------------------------
__device__ __forceinline__ void edge_sd(int t, const int* __restrict__ ei,
                                        int& src, int& dst) {
    if (t < NE) {
        src = ei[2 * t];
        dst = ei[2 * t + 1];
    } else if (t < 2 * NE) {
        int u = t - NE;
        src = ei[2 * u + 1];
        dst = ei[2 * u];
    } else {
        src = dst = t - 2 * NE;
    }
}

// ---------------------------------------------------------------------------
// GEMM body: C[M x BN](fp16) = A[M x K](fp32) * B[K x BN](fp32), fp32 accum.
// 128 x BN tile, 256 threads, 8 x (BN/16) register tile, double-buffered.
// bx = logical block index along M.
// ---------------------------------------------------------------------------
template <int BN, int K>
__device__ __forceinline__ void gemm_body(const float* __restrict__ A,
                                          const float* __restrict__ B,
                                          __half* __restrict__ C,
                                          int M, int bx) {
    constexpr int BM = 128, BK = 8, TN = BN / 16;
    constexpr int NSTEP = K / BK;
    __shared__ float As[2][BK][BM];
    __shared__ float Bs[2][BK][BN];

    const int tid = threadIdx.x;
    const int bm  = bx * BM;
    const int tx  = tid & 15;
    const int ty  = tid >> 4;

    float acc[8][TN];
    #pragma unroll
    for (int i = 0; i < 8; i++)
        #pragma unroll
        for (int j = 0; j < TN; j++) acc[i][j] = 0.f;

    const int a_m = tid >> 1;
    const int a_k = (tid & 1) * 4;
    int a_row = bm + a_m;
    if (a_row >= M) a_row = M - 1;   // clamp: bogus rows never stored
    const float* Aptr = A + (size_t)a_row * K + a_k;

    const int b_k = (BN == 128) ? (tid >> 5) : (tid >> 4);
    const int b_n = (BN == 128) ? ((tid & 31) << 2) : ((tid & 15) << 2);
    const bool b_act = (BN == 128) || (tid < 128);

    float4 av = *reinterpret_cast<const float4*>(Aptr);
    float4 bv = b_act ? *reinterpret_cast<const float4*>(B + (size_t)b_k * BN + b_n)
                      : make_float4(0.f, 0.f, 0.f, 0.f);
    As[0][a_k + 0][a_m] = av.x;
    As[0][a_k + 1][a_m] = av.y;
    As[0][a_k + 2][a_m] = av.z;
    As[0][a_k + 3][a_m] = av.w;
    if (b_act) *reinterpret_cast<float4*>(&Bs[0][b_k][b_n]) = bv;
    __syncthreads();

    int buf = 0;
    #pragma unroll
    for (int step = 0; step < NSTEP; step++) {
        const int k0 = step * BK;
        if (step + 1 < NSTEP) {
            av = *reinterpret_cast<const float4*>(Aptr + k0 + BK);
            if (b_act)
                bv = *reinterpret_cast<const float4*>(
                    B + (size_t)(k0 + BK + b_k) * BN + b_n);
        }
        #pragma unroll
        for (int k = 0; k < BK; k++) {
            float ra[8];
            {
                float4 r0 = *reinterpret_cast<const float4*>(&As[buf][k][ty * 8]);
                float4 r1 = *reinterpret_cast<const float4*>(&As[buf][k][ty * 8 + 4]);
                ra[0] = r0.x; ra[1] = r0.y; ra[2] = r0.z; ra[3] = r0.w;
                ra[4] = r1.x; ra[5] = r1.y; ra[6] = r1.z; ra[7] = r1.w;
            }
            float rb[TN];
            #pragma unroll
            for (int jj = 0; jj < TN; jj += 4) {
                float4 q = *reinterpret_cast<const float4*>(&Bs[buf][k][tx * TN + jj]);
                rb[jj] = q.x; rb[jj + 1] = q.y; rb[jj + 2] = q.z; rb[jj + 3] = q.w;
            }
            #pragma unroll
            for (int i = 0; i < 8; i++)
                #pragma unroll
                for (int j = 0; j < TN; j++)
                    acc[i][j] = fmaf(ra[i], rb[j], acc[i][j]);
        }
        if (step + 1 < NSTEP) {
            const int nb = buf ^ 1;
            As[nb][a_k + 0][a_m] = av.x;
            As[nb][a_k + 1][a_m] = av.y;
            As[nb][a_k + 2][a_m] = av.z;
            As[nb][a_k + 3][a_m] = av.w;
            if (b_act) *reinterpret_cast<float4*>(&Bs[nb][b_k][b_n]) = bv;
            __syncthreads();
            buf = nb;
        }
    }

    #pragma unroll
    for (int i = 0; i < 8; i++) {
        int row = bm + ty * 8 + i;
        if (row < M) {
            __half2* cp = reinterpret_cast<__half2*>(C + (size_t)row * BN + tx * TN);
            #pragma unroll
            for (int j = 0; j < TN; j += 2)
                cp[j >> 1] = __floats2half2_rn(acc[i][j], acc[i][j + 1]);
        }
    }
}

// ---------------------------------------------------------------------------
// Fused: sgemm1 (x@Wg1 -> h1 fp16)  |  hist  |  copy x into xf left half
// (all depend only on kernel inputs; memset(g_deg) precedes this launch)
// ---------------------------------------------------------------------------
__global__ void __launch_bounds__(256)
k_pre(const float* __restrict__ x, const int* __restrict__ ei,
      const float* __restrict__ Wg1, __half* __restrict__ h1) {
    const int bx = blockIdx.x;
    if (bx < GB128) {
        gemm_body<128, 64>(x, Wg1, h1, NN, bx);
    } else if (bx < GB128 + HISTB) {
        const int b = bx - GB128;
        for (int t = b * 256 + threadIdx.x; t < ET; t += HISTB * 256) {
            int s, d;
            edge_sd(t, ei, s, d);
            atomicAdd(&g_deg[d], 1);
        }
    } else {
        const int b = bx - GB128 - HISTB;
        const int total = NN * 16;
        for (int i = b * 256 + threadIdx.x; i < total; i += COPYB * 256) {
            int n = i >> 4, q = i & 15;
            *reinterpret_cast<float4*>(g_xf + (size_t)n * 128 + q * 4) =
                reinterpret_cast<const float4*>(x)[i];
        }
    }
}

// ---------------------------------------------------------------------------
// Single-block scan (+ w~2 projection vectors in spare lanes)
// ---------------------------------------------------------------------------
__global__ void __launch_bounds__(1024)
k_scan(const float* __restrict__ Wg2, const float* __restrict__ a2s,
       const float* __restrict__ a2d) {
    constexpr int CH = (NN + 1023) / 1024;
    __shared__ int wsum[32];
    const int tid  = threadIdx.x;
    const int lane = tid & 31;
    const int wid  = tid >> 5;
    const int base = tid * CH;

    // w~2: s2 = f1 @ (Wg2 @ a2s)   (exact reassociation)
    if (tid < 128) {
        float ws = 0.f, wd = 0.f;
        const float* r = Wg2 + tid * 64;
        #pragma unroll 8
        for (int j = 0; j < 64; j++) {
            float v = r[j];
            ws = fmaf(v, __ldg(a2s + j), ws);
            wd = fmaf(v, __ldg(a2d + j), wd);
        }
        g_w2s[tid] = ws;
        g_w2d[tid] = wd;
    }

    int vals[CH];
    int s = 0;
    #pragma unroll
    for (int k = 0; k < CH; k++) {
        int i = base + k;
        int v = (i < NN) ? g_deg[i] : 0;
        vals[k] = v;
        s += v;
    }
    int x = s;
    #pragma unroll
    for (int off = 1; off < 32; off <<= 1) {
        int y = __shfl_up_sync(0xffffffffu, x, off);
        if (lane >= off) x += y;
    }
    if (lane == 31) wsum[wid] = x;
    __syncthreads();
    if (wid == 0) {
        int w = wsum[lane];
        #pragma unroll
        for (int off = 1; off < 32; off <<= 1) {
            int y = __shfl_up_sync(0xffffffffu, w, off);
            if (lane >= off) w += y;
        }
        wsum[lane] = w;
    }
    __syncthreads();

    int run = x - s + (wid ? wsum[wid - 1] : 0);
    if (tid == 0) g_rowptr[0] = 0;
    #pragma unroll
    for (int k = 0; k < CH; k++) {
        int i = base + k;
        if (i < NN) {
            g_cursor[i] = run;
            run += vals[k];
            g_rowptr[i + 1] = run;
        }
    }
}

// ---------------------------------------------------------------------------
// Fused: CSR fill  |  rowdots1 (h1 fp16, a1 vectors)
// ---------------------------------------------------------------------------
__global__ void __launch_bounds__(256)
k_fill_rd(const int* __restrict__ ei,
          const float* __restrict__ a1s, const float* __restrict__ a1d) {
    const int bx = blockIdx.x;
    if (bx < HISTB) {
        for (int t = bx * 256 + threadIdx.x; t < ET; t += HISTB * 256) {
            int s, d;
            edge_sd(t, ei, s, d);
            int pos = atomicAdd(&g_cursor[d], 1);
            g_adj[pos] = s;
        }
    } else {
        const int w = ((bx - HISTB) * 256 + threadIdx.x) >> 5;
        const int lane = threadIdx.x & 31;
        if (w >= NN) return;
        const __half2* hr = reinterpret_cast<const __half2*>(
            (const __half*)g_h1 + (size_t)w * 128);
        float ds = 0.f, dt = 0.f;
        #pragma unroll
        for (int p = lane; p < 64; p += 32) {
            float2 v = __half22float2(hr[p]);
            ds = fmaf(v.x, __ldg(a1s + 2 * p), fmaf(v.y, __ldg(a1s + 2 * p + 1), ds));
            dt = fmaf(v.x, __ldg(a1d + 2 * p), fmaf(v.y, __ldg(a1d + 2 * p + 1), dt));
        }
        #pragma unroll
        for (int o = 16; o; o >>= 1) {
            ds += __shfl_xor_sync(0xffffffffu, ds, o);
            dt += __shfl_xor_sync(0xffffffffu, dt, o);
        }
        if (lane == 0) { g_s1[w] = ds; g_t1[w] = dt; }
    }
}

// ---------------------------------------------------------------------------
// GAT aggregation, warp per dst node, single pass.
// ---------------------------------------------------------------------------
template <int C>
__global__ void k_gatagg(const __half* __restrict__ h,
                         const float* __restrict__ s,
                         const float* __restrict__ t,
                         const float* __restrict__ bias,
                         float* __restrict__ out, int ostride, int ocoloff) {
    constexpr int CPL = C / 32;
    int w = (blockIdx.x * blockDim.x + threadIdx.x) >> 5;
    int lane = threadIdx.x & 31;
    if (w >= NN) return;

    const int beg = g_rowptr[w];
    const int end = g_rowptr[w + 1];
    const float tn = t[w];

    float denom = 0.f;
    float acc[CPL];
    #pragma unroll
    for (int q = 0; q < CPL; q++) acc[q] = 0.f;

    for (int j0 = beg; j0 < end; j0 += 32) {
        int j = j0 + lane;
        float wv = 0.f;
        int sj = 0;
        if (j < end) {
            sj = g_adj[j];
            float e = s[sj] + tn;
            e = (e >= 0.f) ? e : 0.2f * e;
            wv = __expf(e);
        }
        denom += wv;
        int cnt = end - j0;
        if (cnt > 32) cnt = 32;
        for (int k = 0; k < cnt; k++) {
            float wk = __shfl_sync(0xffffffffu, wv, k);
            int   sk = __shfl_sync(0xffffffffu, sj, k);
            if (CPL == 4) {
                uint2 raw = *reinterpret_cast<const uint2*>(
                    h + (size_t)sk * C + lane * 4);
                float2 lo = __half22float2(*reinterpret_cast<__half2*>(&raw.x));
                float2 hi = __half22float2(*reinterpret_cast<__half2*>(&raw.y));
                acc[0] = fmaf(wk, lo.x, acc[0]);
                acc[1] = fmaf(wk, lo.y, acc[1]);
                acc[2] = fmaf(wk, hi.x, acc[2]);
                acc[3] = fmaf(wk, hi.y, acc[3]);
            } else {
                __half2 raw = *reinterpret_cast<const __half2*>(
                    h + (size_t)sk * C + lane * 2);
                float2 v = __half22float2(raw);
                acc[0] = fmaf(wk, v.x, acc[0]);
                acc[1] = fmaf(wk, v.y, acc[1]);
            }
        }
    }
    #pragma unroll
    for (int o = 16; o; o >>= 1)
        denom += __shfl_xor_sync(0xffffffffu, denom, o);

    const float inv = 1.f / (denom + 1e-16f);
    float* op = out + (size_t)w * ostride + ocoloff + lane * CPL;
    if (CPL == 4) {
        float4 r;
        r.x = fmaxf(acc[0] * inv + __ldg(bias + lane * 4 + 0), 0.f);
        r.y = fmaxf(acc[1] * inv + __ldg(bias + lane * 4 + 1), 0.f);
        r.z = fmaxf(acc[2] * inv + __ldg(bias + lane * 4 + 2), 0.f);
        r.w = fmaxf(acc[3] * inv + __ldg(bias + lane * 4 + 3), 0.f);
        *reinterpret_cast<float4*>(op) = r;
    } else {
        float2 r;
        r.x = fmaxf(acc[0] * inv + __ldg(bias + lane * 2 + 0), 0.f);
        r.y = fmaxf(acc[1] * inv + __ldg(bias + lane * 2 + 1), 0.f);
        *reinterpret_cast<float2*>(op) = r;
    }
}

// ---------------------------------------------------------------------------
// Fused: sgemm2 (f1@Wg2 -> h2 fp16)  |  rowdots2 on f1 with w~2 vectors
// (both depend only on f1)
// ---------------------------------------------------------------------------
__global__ void __launch_bounds__(256)
k_sgemm2_rd(const float* __restrict__ f1, const float* __restrict__ Wg2,
            __half* __restrict__ h2) {
    const int bx = blockIdx.x;
    if (bx < GB128) {
        gemm_body<64, 128>(f1, Wg2, h2, NN, bx);
    } else {
        const int w = ((bx - GB128) * 256 + threadIdx.x) >> 5;
        const int lane = threadIdx.x & 31;
        if (w >= NN) return;
        float4 v  = *reinterpret_cast<const float4*>(f1 + (size_t)w * 128 + lane * 4);
        float4 ws = *reinterpret_cast<const float4*>(g_w2s + lane * 4);
        float4 wd = *reinterpret_cast<const float4*>(g_w2d + lane * 4);
        float ds = v.x * ws.x + v.y * ws.y + v.z * ws.z + v.w * ws.w;
        float dt = v.x * wd.x + v.y * wd.y + v.z * wd.z + v.w * wd.w;
        #pragma unroll
        for (int o = 16; o; o >>= 1) {
            ds += __shfl_xor_sync(0xffffffffu, ds, o);
            dt += __shfl_xor_sync(0xffffffffu, dt, o);
        }
        if (lane == 0) { g_s2[w] = ds; g_t2[w] = dt; }
    }
}

// ---------------------------------------------------------------------------
// Fused U & V GEMMs: blockIdx.y selects which half of W_m1 / which output.
// ---------------------------------------------------------------------------
__global__ void __launch_bounds__(256)
k_uv(const float* __restrict__ xf, const float* __restrict__ Wm1,
     __half* __restrict__ U, __half* __restrict__ V) {
    if (blockIdx.y == 0)
        gemm_body<128, 128>(xf, Wm1, U, NN, blockIdx.x);
    else
        gemm_body<128, 128>(xf, Wm1 + 128 * 128, V, NN, blockIdx.x);
}

// ---------------------------------------------------------------------------
// Edge MLP: W_d in registers (64/lane), warp processes a chunk of edges,
// edge_dist broadcast via shuffles. No per-edge smem traffic.
// ---------------------------------------------------------------------------
__global__ void __launch_bounds__(256)
k_edgemlp(const int* __restrict__ ei, const float* __restrict__ ed,
          const __half* __restrict__ U, const __half* __restrict__ V,
          const float* __restrict__ Wm1, const float* __restrict__ b1,
          const float* __restrict__ Wm2, const float* __restrict__ b2,
          float* __restrict__ out) {
    __shared__ float sWd[16 * 128];
    const int tid = threadIdx.x;
    for (int i = tid; i < 16 * 128; i += 256)
        sWd[i] = Wm1[256 * 128 + i];       // rows 256..271 of W_m1
    __syncthreads();

    const int lane = tid & 31;

    // per-lane weights in registers
    float wd[16][4];
    #pragma unroll
    for (int k = 0; k < 16; k++) {
        float4 q = *reinterpret_cast<const float4*>(sWd + k * 128 + lane * 4);
        wd[k][0] = q.x; wd[k][1] = q.y; wd[k][2] = q.z; wd[k][3] = q.w;
    }
    float4 b1r = *reinterpret_cast<const float4*>(b1 + lane * 4);
    float4 w2r = *reinterpret_cast<const float4*>(Wm2 + lane * 4);
    const float b2v = __ldg(b2);

    // contiguous edge chunk per warp
    const int gw  = (blockIdx.x * 256 + tid) >> 5;   // global warp id
    const int nw  = MLPB * 8;
    const int epw = (NE + nw - 1) / nw;              // 49
    const int e0  = gw * epw;
    const int e1  = (e0 + epw < NE) ? e0 + epw : NE;

    for (int e = e0; e < e1; e++) {
        int2 rc = *reinterpret_cast<const int2*>(ei + 2 * e);

        float edv = (lane < 16) ? __ldg(ed + (size_t)e * 16 + lane) : 0.f;

        uint2 ur = *reinterpret_cast<const uint2*>(U + (size_t)rc.x * 128 + lane * 4);
        uint2 vr = *reinterpret_cast<const uint2*>(V + (size_t)rc.y * 128 + lane * 4);
        float2 u01 = __half22float2(*reinterpret_cast<__half2*>(&ur.x));
        float2 u23 = __half22float2(*reinterpret_cast<__half2*>(&ur.y));
        float2 v01 = __half22float2(*reinterpret_cast<__half2*>(&vr.x));
        float2 v23 = __half22float2(*reinterpret_cast<__half2*>(&vr.y));

        float a0 = u01.x + v01.x + b1r.x;
        float a1 = u01.y + v01.y + b1r.y;
        float a2 = u23.x + v23.x + b1r.z;
        float a3 = u23.y + v23.y + b1r.w;

        #pragma unroll
        for (int k = 0; k < 16; k++) {
            float dk = __shfl_sync(0xffffffffu, edv, k);
            a0 = fmaf(dk, wd[k][0], a0);
            a1 = fmaf(dk, wd[k][1], a1);
            a2 = fmaf(dk, wd[k][2], a2);
            a3 = fmaf(dk, wd[k][3], a3);
        }
        a0 = fmaxf(a0, 0.f); a1 = fmaxf(a1, 0.f);
        a2 = fmaxf(a2, 0.f); a3 = fmaxf(a3, 0.f);

        float p = a0 * w2r.x + a1 * w2r.y + a2 * w2r.z + a3 * w2r.w;
        #pragma unroll
        for (int o = 16; o; o >>= 1)
            p += __shfl_xor_sync(0xffffffffu, p, o);

        if (lane == 0)
            out[e] = 1.f / (1.f + __expf(-(p + b2v)));
    }
}

// ---------------------------------------------------------------------------
extern "C" void kernel_launch(void* const* d_in, const int* in_sizes, int n_in,
                              void* d_out, int out_size) {
    const float* x    = (const float*)d_in[0];
    const int*   ei   = (const int*)  d_in[1];
    const float* ed   = (const float*)d_in[2];
    const float* Wg1  = (const float*)d_in[3];
    const float* a1s  = (const float*)d_in[4];
    const float* a1d  = (const float*)d_in[5];
    const float* bg1  = (const float*)d_in[6];
    const float* Wg2  = (const float*)d_in[7];
    const float* a2s  = (const float*)d_in[8];
    const float* a2d  = (const float*)d_in[9];
    const float* bg2  = (const float*)d_in[10];
    const float* Wm1  = (const float*)d_in[11];
    const float* bm1  = (const float*)d_in[12];
    const float* Wm2  = (const float*)d_in[13];
    const float* bm2  = (const float*)d_in[14];
    float* out = (float*)d_out;

    __half *h1, *h2, *U, *V;
    float *f1, *xf, *s1, *t1, *s2, *t2;
    int* degp;
    cudaGetSymbolAddress((void**)&h1, g_h1);
    cudaGetSymbolAddress((void**)&h2, g_h2);
    cudaGetSymbolAddress((void**)&U,  g_U);
    cudaGetSymbolAddress((void**)&V,  g_V);
    cudaGetSymbolAddress((void**)&f1, g_f1);
    cudaGetSymbolAddress((void**)&xf, g_xf);
    cudaGetSymbolAddress((void**)&s1, g_s1);
    cudaGetSymbolAddress((void**)&t1, g_t1);
    cudaGetSymbolAddress((void**)&s2, g_s2);
    cudaGetSymbolAddress((void**)&t2, g_t2);
    cudaGetSymbolAddress((void**)&degp, g_deg);

    cudaMemsetAsync(degp, 0, NN * sizeof(int));

    // sgemm1 | hist | copyx
    k_pre<<<GB128 + HISTB + COPYB, 256>>>(x, ei, Wg1, h1);
    // scan + w~2
    k_scan<<<1, 1024>>>(Wg2, a2s, a2d);
    // fill | rowdots1
    k_fill_rd<<<HISTB + WB, 256>>>(ei, a1s, a1d);
    // GAT aggregate 1 -> f1
    k_gatagg<128><<<WB, 256>>>(h1, s1, t1, bg1, f1, 128, 0);
    // sgemm2 | rowdots2
    k_sgemm2_rd<<<GB128 + WB, 256>>>(f1, Wg2, h2);
    // GAT aggregate 2 -> xf right half
    k_gatagg<64><<<WB, 256>>>(h2, s2, t2, bg2, xf, 128, 64);
    // U and V GEMMs fused
    k_uv<<<dim3(GB128, 2), 256>>>(xf, Wm1, U, V);
    // edge MLP
    k_edgemlp<<<MLPB, 256>>>(ei, ed, U, V, Wm1, bm1, Wm2, bm2, out);
}

// round 7
// speedup vs baseline: 1.3599x; 1.1867x over previous
#include <cuda_runtime.h>
#include <cuda_fp16.h>
#include <mma.h>
#include <math.h>

using namespace nvcuda;

// ---------------------------------------------------------------------------
// GATEdgeNet: 2x GATConv (single head) + edge MLP.
//  - ALL dense GEMMs on tensor cores (wmma fp16 in / fp32 accum / fp16 out)
//  - gathered tensors (h1,h2,U,V) in fp16
//  - single-pass GAT softmax (shift-invariant, bounded logits)
//  - edge MLP with W_d in registers
//  - independent kernels fused by grid concatenation
// ---------------------------------------------------------------------------

constexpr int NN  = 50000;
constexpr int NNP = 50048;                 // padded to 128-row multiple (391*128)
constexpr int NE  = 800000;
constexpr int ET  = 2 * NE + NN;           // 1,650,000

constexpr int GB128 = NNP / 128;           // 391 gemm blocks
constexpr int WB    = (NN * 32 + 255) / 256;  // 6250 warp-per-node blocks
constexpr int HISTB = 2048;
constexpr int COPYB = 1024;
constexpr int MLPB  = 2048;

// ---- scratch (static device arrays; no runtime alloc allowed) --------------
__device__ __half g_h1[NNP * 128];
__device__ __half g_h2[NNP * 64];
__device__ __half g_U[NNP * 128];
__device__ __half g_V[NNP * 128];
__device__ float g_f1[NN * 128];
__device__ float g_xf[NN * 128];
__device__ float g_s1[NN];
__device__ float g_t1[NN];
__device__ float g_s2[NN];
__device__ float g_t2[NN];
__device__ float g_w2s[128];
__device__ float g_w2d[128];
__device__ int   g_deg[NN];
__device__ int   g_rowptr[NN + 1];
__device__ int   g_cursor[NN];
__device__ int   g_adj[ET];

// ---------------------------------------------------------------------------
__device__ __forceinline__ void edge_sd(int t, const int* __restrict__ ei,
                                        int& src, int& dst) {
    if (t < NE) {
        src = ei[2 * t];
        dst = ei[2 * t + 1];
    } else if (t < 2 * NE) {
        int u = t - NE;
        src = ei[2 * u + 1];
        dst = ei[2 * u];
    } else {
        src = dst = t - 2 * NE;
    }
}

// ---------------------------------------------------------------------------
// Tensor-core GEMM body: C[NNP x BN](fp16) = A[M x K](fp32) * B[K x BN](fp32)
// fp32 accumulate. 256 threads = 8 warps, block tile 128 x BN.
// B converted to fp16 smem once; A staged fp32->fp16 16 cols at a time.
// Stores bounce through per-warp smem float scratch (safe element mapping).
// ---------------------------------------------------------------------------
template <int K, int BN>
__device__ __forceinline__ void gemm_wmma(const float* __restrict__ A,
                                          const float* __restrict__ B,
                                          __half* __restrict__ C,
                                          int M, int bx) {
    constexpr int BM = 128;
    constexpr int WN = (BN == 128) ? 4 : 2;   // warp-grid cols
    constexpr int WM = 8 / WN;                // warp-grid rows
    constexpr int TM = BM / WM;               // warp tile m
    constexpr int TN = BN / WN;               // warp tile n (32)
    constexpr int FM = TM / 16;
    constexpr int FN = TN / 16;

    __shared__ __half sB[K * BN];
    __shared__ __half sA[BM * 16];
    __shared__ float  sC[8][256];

    const int tid  = threadIdx.x;
    const int lane = tid & 31;
    const int wid  = tid >> 5;
    const int wm   = wid / WN, wn = wid % WN;
    const int bm   = bx * BM;

    // B -> fp16 smem (whole K x BN)
    for (int i = tid; i < K * BN; i += 256)
        sB[i] = __float2half(B[i]);

    wmma::fragment<wmma::accumulator, 16, 16, 16, float> acc[FM][FN];
    #pragma unroll
    for (int i = 0; i < FM; i++)
        #pragma unroll
        for (int j = 0; j < FN; j++)
            wmma::fill_fragment(acc[i][j], 0.f);

    #pragma unroll
    for (int k0 = 0; k0 < K; k0 += 16) {
        __syncthreads();
        // stage A tile 128 x 16 (fp32 -> fp16), clamp rows >= M
        #pragma unroll
        for (int i = tid; i < BM * 16; i += 256) {
            int r = i >> 4, c = i & 15;
            int row = bm + r;
            if (row >= M) row = M - 1;
            sA[i] = __float2half(A[(size_t)row * K + k0 + c]);
        }
        __syncthreads();

        wmma::fragment<wmma::matrix_a, 16, 16, 16, __half, wmma::row_major> af[FM];
        #pragma unroll
        for (int i = 0; i < FM; i++)
            wmma::load_matrix_sync(af[i], sA + (wm * TM + i * 16) * 16, 16);
        wmma::fragment<wmma::matrix_b, 16, 16, 16, __half, wmma::row_major> bf[FN];
        #pragma unroll
        for (int j = 0; j < FN; j++)
            wmma::load_matrix_sync(bf[j], sB + k0 * BN + wn * TN + j * 16, BN);
        #pragma unroll
        for (int i = 0; i < FM; i++)
            #pragma unroll
            for (int j = 0; j < FN; j++)
                wmma::mma_sync(acc[i][j], af[i], bf[j], acc[i][j]);
    }

    // store: acc -> smem(float) -> global fp16
    float* scw = sC[wid];
    const int r  = lane >> 1;
    const int c0 = (lane & 1) * 8;
    #pragma unroll
    for (int i = 0; i < FM; i++)
        #pragma unroll
        for (int j = 0; j < FN; j++) {
            wmma::store_matrix_sync(scw, acc[i][j], 16, wmma::mem_row_major);
            __syncwarp();
            float4 p0 = *reinterpret_cast<float4*>(scw + r * 16 + c0);
            float4 p1 = *reinterpret_cast<float4*>(scw + r * 16 + c0 + 4);
            __half2 h[4];
            h[0] = __floats2half2_rn(p0.x, p0.y);
            h[1] = __floats2half2_rn(p0.z, p0.w);
            h[2] = __floats2half2_rn(p1.x, p1.y);
            h[3] = __floats2half2_rn(p1.z, p1.w);
            __half* cp = C + (size_t)(bm + wm * TM + i * 16 + r) * BN
                           + wn * TN + j * 16 + c0;
            *reinterpret_cast<uint4*>(cp) = *reinterpret_cast<uint4*>(h);
            __syncwarp();
        }
}

// ---------------------------------------------------------------------------
// Fused: gemm1 (x@Wg1 -> h1 fp16, tensor cores)  |  hist  |  copy x into xf
// ---------------------------------------------------------------------------
__global__ void __launch_bounds__(256)
k_pre(const float* __restrict__ x, const int* __restrict__ ei,
      const float* __restrict__ Wg1, __half* __restrict__ h1) {
    const int bx = blockIdx.x;
    if (bx < GB128) {
        gemm_wmma<64, 128>(x, Wg1, h1, NN, bx);
    } else if (bx < GB128 + HISTB) {
        const int b = bx - GB128;
        for (int t = b * 256 + threadIdx.x; t < ET; t += HISTB * 256) {
            int s, d;
            edge_sd(t, ei, s, d);
            atomicAdd(&g_deg[d], 1);
        }
    } else {
        const int b = bx - GB128 - HISTB;
        const int total = NN * 16;
        for (int i = b * 256 + threadIdx.x; i < total; i += COPYB * 256) {
            int n = i >> 4, q = i & 15;
            *reinterpret_cast<float4*>(g_xf + (size_t)n * 128 + q * 4) =
                reinterpret_cast<const float4*>(x)[i];
        }
    }
}

// ---------------------------------------------------------------------------
// Single-block scan (+ w~2 projection vectors in spare lanes)
// ---------------------------------------------------------------------------
__global__ void __launch_bounds__(1024)
k_scan(const float* __restrict__ Wg2, const float* __restrict__ a2s,
       const float* __restrict__ a2d) {
    constexpr int CH = (NN + 1023) / 1024;
    __shared__ int wsum[32];
    const int tid  = threadIdx.x;
    const int lane = tid & 31;
    const int wid  = tid >> 5;
    const int base = tid * CH;

    if (tid < 128) {
        float ws = 0.f, wd = 0.f;
        const float* r = Wg2 + tid * 64;
        #pragma unroll 8
        for (int j = 0; j < 64; j++) {
            float v = r[j];
            ws = fmaf(v, __ldg(a2s + j), ws);
            wd = fmaf(v, __ldg(a2d + j), wd);
        }
        g_w2s[tid] = ws;
        g_w2d[tid] = wd;
    }

    int vals[CH];
    int s = 0;
    #pragma unroll
    for (int k = 0; k < CH; k++) {
        int i = base + k;
        int v = (i < NN) ? g_deg[i] : 0;
        vals[k] = v;
        s += v;
    }
    int x = s;
    #pragma unroll
    for (int off = 1; off < 32; off <<= 1) {
        int y = __shfl_up_sync(0xffffffffu, x, off);
        if (lane >= off) x += y;
    }
    if (lane == 31) wsum[wid] = x;
    __syncthreads();
    if (wid == 0) {
        int w = wsum[lane];
        #pragma unroll
        for (int off = 1; off < 32; off <<= 1) {
            int y = __shfl_up_sync(0xffffffffu, w, off);
            if (lane >= off) w += y;
        }
        wsum[lane] = w;
    }
    __syncthreads();

    int run = x - s + (wid ? wsum[wid - 1] : 0);
    if (tid == 0) g_rowptr[0] = 0;
    #pragma unroll
    for (int k = 0; k < CH; k++) {
        int i = base + k;
        if (i < NN) {
            g_cursor[i] = run;
            run += vals[k];
            g_rowptr[i + 1] = run;
        }
    }
}

// ---------------------------------------------------------------------------
// Fused: CSR fill  |  rowdots1 (h1 fp16, a1 vectors)
// ---------------------------------------------------------------------------
__global__ void __launch_bounds__(256)
k_fill_rd(const int* __restrict__ ei,
          const float* __restrict__ a1s, const float* __restrict__ a1d) {
    const int bx = blockIdx.x;
    if (bx < HISTB) {
        for (int t = bx * 256 + threadIdx.x; t < ET; t += HISTB * 256) {
            int s, d;
            edge_sd(t, ei, s, d);
            int pos = atomicAdd(&g_cursor[d], 1);
            g_adj[pos] = s;
        }
    } else {
        const int w = ((bx - HISTB) * 256 + threadIdx.x) >> 5;
        const int lane = threadIdx.x & 31;
        if (w >= NN) return;
        const __half2* hr = reinterpret_cast<const __half2*>(g_h1 + (size_t)w * 128);
        float ds = 0.f, dt = 0.f;
        #pragma unroll
        for (int p = lane; p < 64; p += 32) {
            float2 v = __half22float2(hr[p]);
            ds = fmaf(v.x, __ldg(a1s + 2 * p), fmaf(v.y, __ldg(a1s + 2 * p + 1), ds));
            dt = fmaf(v.x, __ldg(a1d + 2 * p), fmaf(v.y, __ldg(a1d + 2 * p + 1), dt));
        }
        #pragma unroll
        for (int o = 16; o; o >>= 1) {
            ds += __shfl_xor_sync(0xffffffffu, ds, o);
            dt += __shfl_xor_sync(0xffffffffu, dt, o);
        }
        if (lane == 0) { g_s1[w] = ds; g_t1[w] = dt; }
    }
}

// ---------------------------------------------------------------------------
// GAT aggregation, warp per dst node, single pass.
// Full 32-edge chunks get a compile-time unrolled loop (batched gathers).
// ---------------------------------------------------------------------------
template <int C>
__device__ __forceinline__ void gat_accum(const __half* __restrict__ h,
                                          int sk, float wk, int lane,
                                          float* acc) {
    if (C == 128) {
        uint2 raw = *reinterpret_cast<const uint2*>(h + (size_t)sk * C + lane * 4);
        float2 lo = __half22float2(*reinterpret_cast<__half2*>(&raw.x));
        float2 hi = __half22float2(*reinterpret_cast<__half2*>(&raw.y));
        acc[0] = fmaf(wk, lo.x, acc[0]);
        acc[1] = fmaf(wk, lo.y, acc[1]);
        acc[2] = fmaf(wk, hi.x, acc[2]);
        acc[3] = fmaf(wk, hi.y, acc[3]);
    } else {
        __half2 raw = *reinterpret_cast<const __half2*>(h + (size_t)sk * C + lane * 2);
        float2 v = __half22float2(raw);
        acc[0] = fmaf(wk, v.x, acc[0]);
        acc[1] = fmaf(wk, v.y, acc[1]);
    }
}

template <int C>
__global__ void k_gatagg(const __half* __restrict__ h,
                         const float* __restrict__ s,
                         const float* __restrict__ t,
                         const float* __restrict__ bias,
                         float* __restrict__ out, int ostride, int ocoloff) {
    constexpr int CPL = C / 32;
    int w = (blockIdx.x * blockDim.x + threadIdx.x) >> 5;
    int lane = threadIdx.x & 31;
    if (w >= NN) return;

    const int beg = g_rowptr[w];
    const int end = g_rowptr[w + 1];
    const float tn = t[w];

    float denom = 0.f;
    float acc[CPL];
    #pragma unroll
    for (int q = 0; q < CPL; q++) acc[q] = 0.f;

    int j0 = beg;
    for (; j0 + 32 <= end; j0 += 32) {          // full chunks
        int sj = g_adj[j0 + lane];
        float e = s[sj] + tn;
        e = (e >= 0.f) ? e : 0.2f * e;
        float wv = __expf(e);
        denom += wv;
        #pragma unroll
        for (int k = 0; k < 32; k++) {
            float wk = __shfl_sync(0xffffffffu, wv, k);
            int   sk = __shfl_sync(0xffffffffu, sj, k);
            gat_accum<C>(h, sk, wk, lane, acc);
        }
    }
    if (j0 < end) {                              // remainder
        int j = j0 + lane;
        float wv = 0.f;
        int sj = 0;
        if (j < end) {
            sj = g_adj[j];
            float e = s[sj] + tn;
            e = (e >= 0.f) ? e : 0.2f * e;
            wv = __expf(e);
        }
        denom += wv;
        int cnt = end - j0;
        for (int k = 0; k < cnt; k++) {
            float wk = __shfl_sync(0xffffffffu, wv, k);
            int   sk = __shfl_sync(0xffffffffu, sj, k);
            gat_accum<C>(h, sk, wk, lane, acc);
        }
    }
    #pragma unroll
    for (int o = 16; o; o >>= 1)
        denom += __shfl_xor_sync(0xffffffffu, denom, o);

    const float inv = 1.f / (denom + 1e-16f);
    float* op = out + (size_t)w * ostride + ocoloff + lane * CPL;
    if (CPL == 4) {
        float4 r;
        r.x = fmaxf(acc[0] * inv + __ldg(bias + lane * 4 + 0), 0.f);
        r.y = fmaxf(acc[1] * inv + __ldg(bias + lane * 4 + 1), 0.f);
        r.z = fmaxf(acc[2] * inv + __ldg(bias + lane * 4 + 2), 0.f);
        r.w = fmaxf(acc[3] * inv + __ldg(bias + lane * 4 + 3), 0.f);
        *reinterpret_cast<float4*>(op) = r;
    } else {
        float2 r;
        r.x = fmaxf(acc[0] * inv + __ldg(bias + lane * 2 + 0), 0.f);
        r.y = fmaxf(acc[1] * inv + __ldg(bias + lane * 2 + 1), 0.f);
        *reinterpret_cast<float2*>(op) = r;
    }
}

// ---------------------------------------------------------------------------
// Fused: gemm2 (f1@Wg2 -> h2 fp16, tensor cores)  |  rowdots2 (f1, w~2)
// ---------------------------------------------------------------------------
__global__ void __launch_bounds__(256)
k_sgemm2_rd(const float* __restrict__ f1, const float* __restrict__ Wg2,
            __half* __restrict__ h2) {
    const int bx = blockIdx.x;
    if (bx < GB128) {
        gemm_wmma<128, 64>(f1, Wg2, h2, NN, bx);
    } else {
        const int w = ((bx - GB128) * 256 + threadIdx.x) >> 5;
        const int lane = threadIdx.x & 31;
        if (w >= NN) return;
        float4 v  = *reinterpret_cast<const float4*>(f1 + (size_t)w * 128 + lane * 4);
        float4 ws = *reinterpret_cast<const float4*>(g_w2s + lane * 4);
        float4 wd = *reinterpret_cast<const float4*>(g_w2d + lane * 4);
        float ds = v.x * ws.x + v.y * ws.y + v.z * ws.z + v.w * ws.w;
        float dt = v.x * wd.x + v.y * wd.y + v.z * wd.z + v.w * wd.w;
        #pragma unroll
        for (int o = 16; o; o >>= 1) {
            ds += __shfl_xor_sync(0xffffffffu, ds, o);
            dt += __shfl_xor_sync(0xffffffffu, dt, o);
        }
        if (lane == 0) { g_s2[w] = ds; g_t2[w] = dt; }
    }
}

// ---------------------------------------------------------------------------
// Fused U & V tensor-core GEMMs (blockIdx.y selects half of W_m1 / output)
// ---------------------------------------------------------------------------
__global__ void __launch_bounds__(256)
k_uv(const float* __restrict__ xf, const float* __restrict__ Wm1,
     __half* __restrict__ U, __half* __restrict__ V) {
    if (blockIdx.y == 0)
        gemm_wmma<128, 128>(xf, Wm1, U, NN, blockIdx.x);
    else
        gemm_wmma<128, 128>(xf, Wm1 + 128 * 128, V, NN, blockIdx.x);
}

// ---------------------------------------------------------------------------
// Edge MLP: W_d in registers, warp per edge chunk, shuffled edge_dist.
// ---------------------------------------------------------------------------
__global__ void __launch_bounds__(256)
k_edgemlp(const int* __restrict__ ei, const float* __restrict__ ed,
          const __half* __restrict__ U, const __half* __restrict__ V,
          const float* __restrict__ Wm1, const float* __restrict__ b1,
          const float* __restrict__ Wm2, const float* __restrict__ b2,
          float* __restrict__ out) {
    __shared__ float sWd[16 * 128];
    const int tid = threadIdx.x;
    for (int i = tid; i < 16 * 128; i += 256)
        sWd[i] = Wm1[256 * 128 + i];
    __syncthreads();

    const int lane = tid & 31;

    float wd[16][4];
    #pragma unroll
    for (int k = 0; k < 16; k++) {
        float4 q = *reinterpret_cast<const float4*>(sWd + k * 128 + lane * 4);
        wd[k][0] = q.x; wd[k][1] = q.y; wd[k][2] = q.z; wd[k][3] = q.w;
    }
    float4 b1r = *reinterpret_cast<const float4*>(b1 + lane * 4);
    float4 w2r = *reinterpret_cast<const float4*>(Wm2 + lane * 4);
    const float b2v = __ldg(b2);

    const int gw  = (blockIdx.x * 256 + tid) >> 5;
    const int nw  = MLPB * 8;
    const int epw = (NE + nw - 1) / nw;
    const int e0  = gw * epw;
    const int e1  = (e0 + epw < NE) ? e0 + epw : NE;

    for (int e = e0; e < e1; e++) {
        int2 rc = *reinterpret_cast<const int2*>(ei + 2 * e);
        float edv = (lane < 16) ? __ldg(ed + (size_t)e * 16 + lane) : 0.f;

        uint2 ur = *reinterpret_cast<const uint2*>(U + (size_t)rc.x * 128 + lane * 4);
        uint2 vr = *reinterpret_cast<const uint2*>(V + (size_t)rc.y * 128 + lane * 4);
        float2 u01 = __half22float2(*reinterpret_cast<__half2*>(&ur.x));
        float2 u23 = __half22float2(*reinterpret_cast<__half2*>(&ur.y));
        float2 v01 = __half22float2(*reinterpret_cast<__half2*>(&vr.x));
        float2 v23 = __half22float2(*reinterpret_cast<__half2*>(&vr.y));

        float a0 = u01.x + v01.x + b1r.x;
        float a1 = u01.y + v01.y + b1r.y;
        float a2 = u23.x + v23.x + b1r.z;
        float a3 = u23.y + v23.y + b1r.w;

        #pragma unroll
        for (int k = 0; k < 16; k++) {
            float dk = __shfl_sync(0xffffffffu, edv, k);
            a0 = fmaf(dk, wd[k][0], a0);
            a1 = fmaf(dk, wd[k][1], a1);
            a2 = fmaf(dk, wd[k][2], a2);
            a3 = fmaf(dk, wd[k][3], a3);
        }
        a0 = fmaxf(a0, 0.f); a1 = fmaxf(a1, 0.f);
        a2 = fmaxf(a2, 0.f); a3 = fmaxf(a3, 0.f);

        float p = a0 * w2r.x + a1 * w2r.y + a2 * w2r.z + a3 * w2r.w;
        #pragma unroll
        for (int o = 16; o; o >>= 1)
            p += __shfl_xor_sync(0xffffffffu, p, o);

        if (lane == 0)
            out[e] = 1.f / (1.f + __expf(-(p + b2v)));
    }
}

// ---------------------------------------------------------------------------
extern "C" void kernel_launch(void* const* d_in, const int* in_sizes, int n_in,
                              void* d_out, int out_size) {
    const float* x    = (const float*)d_in[0];
    const int*   ei   = (const int*)  d_in[1];
    const float* ed   = (const float*)d_in[2];
    const float* Wg1  = (const float*)d_in[3];
    const float* a1s  = (const float*)d_in[4];
    const float* a1d  = (const float*)d_in[5];
    const float* bg1  = (const float*)d_in[6];
    const float* Wg2  = (const float*)d_in[7];
    const float* a2s  = (const float*)d_in[8];
    const float* a2d  = (const float*)d_in[9];
    const float* bg2  = (const float*)d_in[10];
    const float* Wm1  = (const float*)d_in[11];
    const float* bm1  = (const float*)d_in[12];
    const float* Wm2  = (const float*)d_in[13];
    const float* bm2  = (const float*)d_in[14];
    float* out = (float*)d_out;

    __half *h1, *h2, *U, *V;
    float *f1, *xf, *s1, *t1, *s2, *t2;
    int* degp;
    cudaGetSymbolAddress((void**)&h1, g_h1);
    cudaGetSymbolAddress((void**)&h2, g_h2);
    cudaGetSymbolAddress((void**)&U,  g_U);
    cudaGetSymbolAddress((void**)&V,  g_V);
    cudaGetSymbolAddress((void**)&f1, g_f1);
    cudaGetSymbolAddress((void**)&xf, g_xf);
    cudaGetSymbolAddress((void**)&s1, g_s1);
    cudaGetSymbolAddress((void**)&t1, g_t1);
    cudaGetSymbolAddress((void**)&s2, g_s2);
    cudaGetSymbolAddress((void**)&t2, g_t2);
    cudaGetSymbolAddress((void**)&degp, g_deg);

    cudaMemsetAsync(degp, 0, NN * sizeof(int));

    // gemm1 | hist | copyx
    k_pre<<<GB128 + HISTB + COPYB, 256>>>(x, ei, Wg1, h1);
    // scan + w~2
    k_scan<<<1, 1024>>>(Wg2, a2s, a2d);
    // fill | rowdots1
    k_fill_rd<<<HISTB + WB, 256>>>(ei, a1s, a1d);
    // GAT aggregate 1 -> f1
    k_gatagg<128><<<WB, 256>>>(h1, s1, t1, bg1, f1, 128, 0);
    // gemm2 | rowdots2
    k_sgemm2_rd<<<GB128 + WB, 256>>>(f1, Wg2, h2);
    // GAT aggregate 2 -> xf right half
    k_gatagg<64><<<WB, 256>>>(h2, s2, t2, bg2, xf, 128, 64);
    // U and V GEMMs
    k_uv<<<dim3(GB128, 2), 256>>>(xf, Wm1, U, V);
    // edge MLP
    k_edgemlp<<<MLPB, 256>>>(ei, ed, U, V, Wm1, bm1, Wm2, bm2, out);
}